// round 1
// baseline (speedup 1.0000x reference)
#include <cuda_runtime.h>
#include <cuda_bf16.h>
#include <math.h>

#define SEQ       2048
#define NRES      2048
#define NIN       128
#define GRID      128      // CTAs in persistent recurrence kernel
#define RPB       16       // rows of W_res per CTA  (GRID*RPB == NRES)
#define THREADS   512      // each thread owns 4 columns (THREADS*4 == NRES)

// ---------------- device globals (no allocations allowed) ----------------
__device__ float    g_U[SEQ * NRES];   // precomputed input projections (16 MB)
__device__ unsigned g_count;           // grid-barrier arrival counter
__device__ unsigned g_gen;             // grid-barrier generation flag

// ---------------- init kernel: reset barrier state each replay ------------
__global__ void esn_init_kernel() {
    g_count = 0u;
    g_gen   = 0u;
}

// ---------------- U = input @ W_in^T  (NT gemm, K=128) --------------------
// 64x64 tile, 256 threads, full K resident in smem.
#define SM_STRIDE 132   // 128 + 4 pad (keeps 16B alignment, breaks bank conflicts)
__global__ void u_gemm_kernel(const float* __restrict__ inp,
                              const float* __restrict__ win) {
    extern __shared__ float sm[];
    float* sA = sm;                      // 64 x SM_STRIDE (input rows)
    float* sB = sm + 64 * SM_STRIDE;     // 64 x SM_STRIDE (W_in rows)

    const int bt  = blockIdx.y * 64;     // time-row base
    const int bn  = blockIdx.x * 64;     // reservoir-row base
    const int tid = threadIdx.x;

    // cooperative load: 64 rows x 32 float4 per matrix
    for (int i = tid; i < 64 * 32; i += 256) {
        const int row = i >> 5;
        const int c4  = i & 31;
        float4 a = ((const float4*)(inp + (size_t)(bt + row) * NIN))[c4];
        float4 b = ((const float4*)(win + (size_t)(bn + row) * NIN))[c4];
        *(float4*)&sA[row * SM_STRIDE + c4 * 4] = a;
        *(float4*)&sB[row * SM_STRIDE + c4 * 4] = b;
    }
    __syncthreads();

    const int tx = tid & 15;
    const int ty = tid >> 4;

    float acc[4][4];
#pragma unroll
    for (int i = 0; i < 4; i++)
#pragma unroll
        for (int j = 0; j < 4; j++) acc[i][j] = 0.0f;

#pragma unroll 4
    for (int k = 0; k < NIN; k += 4) {
        float4 av[4], bv[4];
#pragma unroll
        for (int i = 0; i < 4; i++)
            av[i] = *(const float4*)&sA[(ty * 4 + i) * SM_STRIDE + k];
#pragma unroll
        for (int j = 0; j < 4; j++)
            bv[j] = *(const float4*)&sB[(tx * 4 + j) * SM_STRIDE + k];
#pragma unroll
        for (int i = 0; i < 4; i++)
#pragma unroll
            for (int j = 0; j < 4; j++) {
                acc[i][j] += av[i].x * bv[j].x;
                acc[i][j] += av[i].y * bv[j].y;
                acc[i][j] += av[i].z * bv[j].z;
                acc[i][j] += av[i].w * bv[j].w;
            }
    }

#pragma unroll
    for (int i = 0; i < 4; i++)
#pragma unroll
        for (int j = 0; j < 4; j++)
            g_U[(size_t)(bt + ty * 4 + i) * NRES + (bn + tx * 4 + j)] = acc[i][j];
}

// ---------------- grid barrier (count + generation flag) ------------------
__device__ __forceinline__ void grid_barrier(int t) {
    __syncthreads();
    if (threadIdx.x == 0) {
        __threadfence();                               // make this CTA's stores gpu-visible
        unsigned arrived = atomicAdd(&g_count, 1u) + 1u;
        const unsigned target = (unsigned)t * (unsigned)GRID;
        if (arrived == target) {
            __threadfence();                           // order the RMW-chain before publish
            asm volatile("st.release.gpu.b32 [%0], %1;"
                         :: "l"(&g_gen), "r"((unsigned)t) : "memory");
        } else {
            unsigned g;
            do {
                asm volatile("ld.acquire.gpu.b32 %0, [%1];"
                             : "=r"(g) : "l"(&g_gen) : "memory");
            } while (g < (unsigned)t);
        }
    }
    __syncthreads();
}

// ---------------- persistent recurrence kernel ----------------------------
// CTA b owns rows [b*RPB, (b+1)*RPB) of W_res, held entirely in registers:
// thread tid owns columns [4*tid, 4*tid+4) of each of its 16 rows.
__global__ void __launch_bounds__(THREADS, 1)
esn_recur_kernel(const float* __restrict__ wres, float* __restrict__ out) {
    __shared__ float sRed[16 * 16];      // [warp][row] partials

    const int tid  = threadIdx.x;
    const int lane = tid & 31;
    const int warp = tid >> 5;
    const int row0 = blockIdx.x * RPB;
    const float inv = 0.022097086912079608f;   // 1/sqrt(2048)

    // one-time load of this thread's W_res sub-block into registers (64 regs)
    float4 w[RPB];
#pragma unroll
    for (int r = 0; r < RPB; r++)
        w[r] = ((const float4*)(wres + (size_t)(row0 + r) * NRES))[tid];

    // t = 0 : x0 = erf(U[0]) * inv
    if (tid < RPB) {
        out[row0 + tid] = erff(g_U[row0 + tid]) * inv;
    }

    for (int t = 1; t < SEQ; t++) {
        // prefetch this step's u before the barrier (independent of other CTAs)
        float u_mine = 0.0f;
        if (tid < RPB) u_mine = g_U[(size_t)t * NRES + row0 + tid];

        grid_barrier(t);   // all CTAs have published row t-1

        // load x_{t-1} chunk (4 columns)
        const float4 x = ((const float4*)(out + (size_t)(t - 1) * NRES))[tid];

        // 16 partial dot products (register-resident W)
        float a[RPB];
#pragma unroll
        for (int r = 0; r < RPB; r++) {
            float s = w[r].x * x.x;
            s += w[r].y * x.y;
            s += w[r].z * x.z;
            s += w[r].w * x.w;
            a[r] = s;
        }

        // warp reduction with row-halving butterfly: 16 shfls total.
        // after all steps, lane l holds the warp total for row (l>>1).
        {
            const bool up16 = (lane & 16) != 0;
#pragma unroll
            for (int j = 0; j < 8; j++) {
                float send = up16 ? a[j] : a[j + 8];
                float recv = __shfl_xor_sync(0xffffffffu, send, 16);
                a[j] = (up16 ? a[j + 8] : a[j]) + recv;
            }
            const bool up8 = (lane & 8) != 0;
#pragma unroll
            for (int j = 0; j < 4; j++) {
                float send = up8 ? a[j] : a[j + 4];
                float recv = __shfl_xor_sync(0xffffffffu, send, 8);
                a[j] = (up8 ? a[j + 4] : a[j]) + recv;
            }
            const bool up4 = (lane & 4) != 0;
#pragma unroll
            for (int j = 0; j < 2; j++) {
                float send = up4 ? a[j] : a[j + 2];
                float recv = __shfl_xor_sync(0xffffffffu, send, 4);
                a[j] = (up4 ? a[j + 2] : a[j]) + recv;
            }
            {
                const bool up2 = (lane & 2) != 0;
                float send = up2 ? a[0] : a[1];
                float recv = __shfl_xor_sync(0xffffffffu, send, 2);
                a[0] = (up2 ? a[1] : a[0]) + recv;
            }
            a[0] += __shfl_xor_sync(0xffffffffu, a[0], 1);
        }
        if ((lane & 1) == 0) sRed[warp * 16 + (lane >> 1)] = a[0];
        __syncthreads();

        // cross-warp reduce + activation + publish (threads 0..15, one row each)
        if (tid < RPB) {
            float s = 0.0f;
#pragma unroll
            for (int ww = 0; ww < 16; ww++) s += sRed[ww * 16 + tid];
            out[(size_t)t * NRES + row0 + tid] = erff(u_mine + s) * inv;
        }
        // note: next iteration's grid_barrier starts with __syncthreads(),
        // which separates this iteration's sRed reads from the next writes.
    }
}

// ---------------- launch ---------------------------------------------------
extern "C" void kernel_launch(void* const* d_in, const int* in_sizes, int n_in,
                              void* d_out, int out_size) {
    (void)in_sizes; (void)n_in; (void)out_size;
    const float* input = (const float*)d_in[0];   // (SEQ, NIN)
    const float* win   = (const float*)d_in[1];   // (NRES, NIN)
    const float* wres  = (const float*)d_in[2];   // (NRES, NRES)
    float*       out   = (float*)d_out;           // (SEQ, NRES)

    const int gemm_smem = 2 * 64 * SM_STRIDE * (int)sizeof(float);  // 67584 B
    cudaFuncSetAttribute(u_gemm_kernel,
                         cudaFuncAttributeMaxDynamicSharedMemorySize, gemm_smem);

    esn_init_kernel<<<1, 1>>>();
    u_gemm_kernel<<<dim3(NRES / 64, SEQ / 64), 256, gemm_smem>>>(input, win);
    esn_recur_kernel<<<GRID, THREADS>>>(wres, out);
}